// round 2
// baseline (speedup 1.0000x reference)
#include <cuda_runtime.h>
#include <math.h>

#define BATCH 2
#define CC 256
#define NN 4096
#define HEADS 32
#define HD 8
#define KTOP 512
#define CN (CC*NN)

// ---------------- scratch (device globals; no allocation) ----------------
__device__ float g_avgmax[BATCH*2*NN];
__device__ float g_scores[BATCH*NN];
__device__ int   g_idx[BATCH*KTOP];
__device__ float g_kfull[BATCH*NN*CC];
__device__ float g_vfull[BATCH*NN*CC];
__device__ float g_q[BATCH*NN*CC];
__device__ float g_kg[BATCH*KTOP*CC];
__device__ float g_vg[BATCH*KTOP*CC];
__device__ float g_attn[BATCH*NN*CC];
__device__ float g_vvol[BATCH*CC*NN];
__device__ float g_dw[BATCH*CC*NN];
__device__ float g_res[BATCH*CC*NN];

// ---------------- 1. channel avg/max reduce ----------------
__global__ void k_reduce(const float* __restrict__ x) {
    int i = blockIdx.x * blockDim.x + threadIdx.x;
    if (i >= BATCH*NN) return;
    int b = i >> 12, n = i & (NN-1);
    const float* p = x + (long)b*CN + n;
    float s = 0.f, mx = -INFINITY;
#pragma unroll 8
    for (int c = 0; c < CC; c++) { float v = p[(long)c*NN]; s += v; mx = fmaxf(mx, v); }
    g_avgmax[(b*2+0)*NN + n] = s * (1.0f/CC);
    g_avgmax[(b*2+1)*NN + n] = mx;
}

// ---------------- 2. 7x7x7 spatial conv (2ch -> 1ch) + sigmoid ----------------
__global__ void k_spa(const float* __restrict__ w_spa) {
    __shared__ float w[686];
    int tid = threadIdx.x;
    for (int l = tid; l < 686; l += blockDim.x) w[l] = w_spa[l];
    __syncthreads();
    int i = blockIdx.x * blockDim.x + tid;
    if (i >= BATCH*NN) return;
    int b = i >> 12, n = i & (NN-1);
    int z = n >> 8, y = (n >> 4) & 15, x0 = n & 15;
    float s = 0.f;
    for (int ci = 0; ci < 2; ci++) {
        const float* in = g_avgmax + (b*2+ci)*NN;
        const float* wc = w + ci*343;
        for (int dz = 0; dz < 7; dz++) {
            int zz = z + dz - 3; if (zz < 0 || zz > 15) continue;
            for (int dy = 0; dy < 7; dy++) {
                int yy = y + dy - 3; if (yy < 0 || yy > 15) continue;
                const float* row = in + zz*256 + yy*16;
                const float* wr = wc + dz*49 + dy*7;
                for (int dx = 0; dx < 7; dx++) {
                    int xx = x0 + dx - 3; if (xx < 0 || xx > 15) continue;
                    s += wr[dx] * row[xx];
                }
            }
        }
    }
    g_scores[i] = 1.0f / (1.0f + __expf(-s));
}

// ---------------- 3. per-batch top-512 via bitonic sort ----------------
__global__ void k_topk() {
    __shared__ float key[NN];
    __shared__ int   val[NN];
    int b = blockIdx.x, tid = threadIdx.x;
    for (int i = tid; i < NN; i += blockDim.x) { key[i] = g_scores[b*NN + i]; val[i] = i; }
    __syncthreads();
    for (int k = 2; k <= NN; k <<= 1) {
        for (int j = k >> 1; j > 0; j >>= 1) {
            for (int i = tid; i < NN; i += blockDim.x) {
                int ixj = i ^ j;
                if (ixj > i) {
                    bool desc = ((i & k) == 0);           // descending overall
                    float a = key[i], c2 = key[ixj];
                    bool sw = desc ? (a < c2) : (a > c2);
                    if (sw) {
                        key[i] = c2; key[ixj] = a;
                        int t = val[i]; val[i] = val[ixj]; val[ixj] = t;
                    }
                }
            }
            __syncthreads();
        }
    }
    for (int i = tid; i < KTOP; i += blockDim.x) g_idx[b*KTOP + i] = val[i];
}

// ---------------- generic tiled SGEMM: C[b][m][j] = A[b][m][:] . Bw[:][j] + bias ----
// A element  : A[b*a_bs + m*a_ms + k*a_ks]   (one of a_ms,a_ks must be 1)
// Bw element : Bw[b*w_bs + k*ldb + j]
// C element  : C[b*c_bs + m*c_ms + j*c_js]
// M = gridDim.y*64, J = gridDim.x*64
__global__ void __launch_bounds__(256) k_sgemm(
    const float* __restrict__ A, long a_ms, long a_ks, long a_bs,
    const float* __restrict__ Bw, int ldb, long w_bs,
    const float* __restrict__ bias_j, const float* __restrict__ bias_m,
    float* __restrict__ Cc, long c_ms, long c_js, long c_bs,
    int K)
{
    __shared__ float As[16][64];
    __shared__ float Bs[16][64];
    int b = blockIdx.z;
    const float* Ab = A + (long)b * a_bs;
    const float* Bb = Bw + (long)b * w_bs;
    int m0 = blockIdx.y * 64, j0 = blockIdx.x * 64;
    int tid = threadIdx.x;
    int tm = (tid & 15) << 2, tj = (tid >> 4) << 2;
    float acc[4][4] = {};
    for (int k0 = 0; k0 < K; k0 += 16) {
        if (a_ks == 1) {               // row-major A (k contiguous)
#pragma unroll
            for (int r = 0; r < 4; r++) {
                int l = tid + r * 256;
                int kk = l & 15, mm = l >> 4;
                As[kk][mm] = Ab[(long)(m0+mm)*a_ms + (k0+kk)];
            }
        } else {                       // m contiguous (a_ms == 1)
#pragma unroll
            for (int r = 0; r < 4; r++) {
                int l = tid + r * 256;
                int mm = l & 63, kk = l >> 6;
                As[kk][mm] = Ab[(long)(k0+kk)*a_ks + (m0+mm)];
            }
        }
#pragma unroll
        for (int r = 0; r < 4; r++) {
            int l = tid + r * 256;
            int jj = l & 63, kk = l >> 6;
            Bs[kk][jj] = Bb[(long)(k0+kk)*ldb + (j0+jj)];
        }
        __syncthreads();
#pragma unroll
        for (int kk = 0; kk < 16; kk++) {
            float4 ar = *(const float4*)&As[kk][tm];
            float4 br = *(const float4*)&Bs[kk][tj];
            float a4[4] = {ar.x, ar.y, ar.z, ar.w};
            float b4[4] = {br.x, br.y, br.z, br.w};
#pragma unroll
            for (int ii = 0; ii < 4; ii++)
#pragma unroll
                for (int jj = 0; jj < 4; jj++)
                    acc[ii][jj] += a4[ii] * b4[jj];
        }
        __syncthreads();
    }
    float bj[4] = {0,0,0,0}, bm[4] = {0,0,0,0};
    if (bias_j) { for (int jj = 0; jj < 4; jj++) bj[jj] = bias_j[j0+tj+jj]; }
    if (bias_m) { for (int ii = 0; ii < 4; ii++) bm[ii] = bias_m[m0+tm+ii]; }
#pragma unroll
    for (int ii = 0; ii < 4; ii++)
#pragma unroll
        for (int jj = 0; jj < 4; jj++)
            Cc[(long)b*c_bs + (long)(m0+tm+ii)*c_ms + (long)(j0+tj+jj)*c_js]
                = acc[ii][jj] + bj[jj] + bm[ii];
}

// ---------------- 4. gather top-k K/V rows into compact buffers ----------------
__global__ void k_gather() {
    int t = blockIdx.x * blockDim.x + threadIdx.x;   // BATCH*KTOP*64
    if (t >= BATCH*KTOP*64) return;
    int c4 = t & 63, k = (t >> 6) & (KTOP-1), b = t >> 15;
    int src = g_idx[b*KTOP + k];
    long so = ((long)b*NN + src)*CC + c4*4;
    long dofs = ((long)b*KTOP + k)*CC + c4*4;
    *(float4*)(g_kg + dofs) = *(const float4*)(g_kfull + so);
    *(float4*)(g_vg + dofs) = *(const float4*)(g_vfull + so);
}

// ---------------- 5. transpose v_full (B,N,C) -> (B,C,N) ----------------
__global__ void k_transpose() {
    __shared__ float tile[32][33];
    int b = blockIdx.z;
    int n0 = blockIdx.x * 32, c0 = blockIdx.y * 32;
    const float* inb = g_vfull + (long)b*CN;
    float* outb = g_vvol + (long)b*CN;
    int tx = threadIdx.x, ty0 = threadIdx.y;
    for (int dy = 0; dy < 32; dy += 8) {
        int ty = ty0 + dy;
        tile[ty][tx] = inb[(long)(n0+ty)*CC + c0 + tx];
    }
    __syncthreads();
    for (int dy = 0; dy < 32; dy += 8) {
        int ty = ty0 + dy;
        outb[(long)(c0+ty)*NN + n0 + tx] = tile[tx][ty];
    }
}

// ---------------- 6. depthwise 3x3x3 conv ----------------
__global__ void k_dwconv(const float* __restrict__ w_dw, const float* __restrict__ b_dw) {
    int i = blockIdx.x * blockDim.x + threadIdx.x;
    if (i >= BATCH*CN) return;
    int n = i & (NN-1); int c = (i >> 12) & (CC-1); int b = i >> 20;
    int x = n & 15, y = (n >> 4) & 15, z = n >> 8;
    const float* base = g_vvol + ((long)b*CC + c)*NN;
    const float* w = w_dw + c*27;
    float s = b_dw[c];
#pragma unroll
    for (int dz = 0; dz < 3; dz++) {
        int zz = z + dz - 1; if (zz < 0 || zz > 15) continue;
#pragma unroll
        for (int dy = 0; dy < 3; dy++) {
            int yy = y + dy - 1; if (yy < 0 || yy > 15) continue;
#pragma unroll
            for (int dx = 0; dx < 3; dx++) {
                int xx = x + dx - 1; if (xx < 0 || xx > 15) continue;
                s += w[dz*9 + dy*3 + dx] * base[zz*256 + yy*16 + xx];
            }
        }
    }
    g_dw[i] = s;
}

// ---------------- 7. attention: online softmax, 4 queries/thread ----------------
__global__ void __launch_bounds__(128) k_attn() {
    __shared__ float Ks[KTOP*HD];   // 16 KB
    __shared__ float Vs[KTOP*HD];   // 16 KB
    int b = blockIdx.z, h = blockIdx.y, nt = blockIdx.x;
    int tid = threadIdx.x;
    const float* kgb = g_kg + (long)b*KTOP*CC + h*HD;
    const float* vgb = g_vg + (long)b*KTOP*CC + h*HD;
    for (int k = tid; k < KTOP; k += 128) {
        *(float4*)(Ks + k*8)     = *(const float4*)(kgb + (long)k*CC);
        *(float4*)(Ks + k*8 + 4) = *(const float4*)(kgb + (long)k*CC + 4);
        *(float4*)(Vs + k*8)     = *(const float4*)(vgb + (long)k*CC);
        *(float4*)(Vs + k*8 + 4) = *(const float4*)(vgb + (long)k*CC + 4);
    }
    __syncthreads();
    const float scale = 0.3535533905932738f;  // 8^-0.5
    float qr[4][8], m[4], l[4], acc[4][8];
    int n0 = nt * 512;
#pragma unroll
    for (int i = 0; i < 4; i++) {
        int n = n0 + tid + 128*i;
        const float* qp = g_q + ((long)b*NN + n)*CC + h*HD;
        float4 qa = *(const float4*)qp;
        float4 qb = *(const float4*)(qp + 4);
        qr[i][0]=qa.x*scale; qr[i][1]=qa.y*scale; qr[i][2]=qa.z*scale; qr[i][3]=qa.w*scale;
        qr[i][4]=qb.x*scale; qr[i][5]=qb.y*scale; qr[i][6]=qb.z*scale; qr[i][7]=qb.w*scale;
        m[i] = -INFINITY; l[i] = 0.f;
#pragma unroll
        for (int d = 0; d < 8; d++) acc[i][d] = 0.f;
    }
    for (int k = 0; k < KTOP; k++) {
        float4 ka = *(const float4*)(Ks + k*8);
        float4 kb = *(const float4*)(Ks + k*8 + 4);
        float4 va = *(const float4*)(Vs + k*8);
        float4 vb = *(const float4*)(Vs + k*8 + 4);
#pragma unroll
        for (int i = 0; i < 4; i++) {
            float s = qr[i][0]*ka.x + qr[i][1]*ka.y + qr[i][2]*ka.z + qr[i][3]*ka.w
                    + qr[i][4]*kb.x + qr[i][5]*kb.y + qr[i][6]*kb.z + qr[i][7]*kb.w;
            if (s > m[i]) {
                float corr = __expf(m[i] - s);
                m[i] = s;
                l[i] = l[i]*corr + 1.0f;
                acc[i][0] = acc[i][0]*corr + va.x;
                acc[i][1] = acc[i][1]*corr + va.y;
                acc[i][2] = acc[i][2]*corr + va.z;
                acc[i][3] = acc[i][3]*corr + va.w;
                acc[i][4] = acc[i][4]*corr + vb.x;
                acc[i][5] = acc[i][5]*corr + vb.y;
                acc[i][6] = acc[i][6]*corr + vb.z;
                acc[i][7] = acc[i][7]*corr + vb.w;
            } else {
                float p = __expf(s - m[i]);
                l[i] += p;
                acc[i][0] += p*va.x; acc[i][1] += p*va.y;
                acc[i][2] += p*va.z; acc[i][3] += p*va.w;
                acc[i][4] += p*vb.x; acc[i][5] += p*vb.y;
                acc[i][6] += p*vb.z; acc[i][7] += p*vb.w;
            }
        }
    }
#pragma unroll
    for (int i = 0; i < 4; i++) {
        int n = n0 + tid + 128*i;
        float inv = 1.0f / l[i];
        float* op = g_attn + ((long)b*NN + n)*CC + h*HD;
        float4 o1 = make_float4(acc[i][0]*inv, acc[i][1]*inv, acc[i][2]*inv, acc[i][3]*inv);
        float4 o2 = make_float4(acc[i][4]*inv, acc[i][5]*inv, acc[i][6]*inv, acc[i][7]*inv);
        *(float4*)op = o1;
        *(float4*)(op + 4) = o2;
    }
}

// ---------------- 8. final add: out += residual ----------------
__global__ void k_add(float* __restrict__ out) {
    int i = blockIdx.x * blockDim.x + threadIdx.x;
    if (i < BATCH*CN) out[i] += g_res[i];
}

// ---------------- launcher ----------------
extern "C" void kernel_launch(void* const* d_in, const int* in_sizes, int n_in,
                              void* d_out, int out_size) {
    const float* x_kv  = (const float*)d_in[0];
    const float* x_q   = (const float*)d_in[1];
    const float* w_spa = (const float*)d_in[2];
    const float* w_kv  = (const float*)d_in[3];
    const float* b_kv  = (const float*)d_in[4];
    const float* w_q   = (const float*)d_in[5];
    const float* b_q   = (const float*)d_in[6];
    const float* w_proj= (const float*)d_in[7];
    const float* b_proj= (const float*)d_in[8];
    const float* w_dw  = (const float*)d_in[9];
    const float* b_dw  = (const float*)d_in[10];
    const float* w_pw  = (const float*)d_in[11];
    const float* b_pw  = (const float*)d_in[12];
    float* out = (float*)d_out;

    float *kfull, *vfull, *q, *attn, *dw, *res;
    cudaGetSymbolAddress((void**)&kfull, g_kfull);
    cudaGetSymbolAddress((void**)&vfull, g_vfull);
    cudaGetSymbolAddress((void**)&q,     g_q);
    cudaGetSymbolAddress((void**)&attn,  g_attn);
    cudaGetSymbolAddress((void**)&dw,    g_dw);
    cudaGetSymbolAddress((void**)&res,   g_res);

    // scoring path
    k_reduce<<<32, 256>>>(x_kv);
    k_spa<<<32, 256>>>(w_spa);
    k_topk<<<2, 1024>>>();

    // projections: A = x (m=n contiguous, k=c strided by N)
    dim3 gkv(4, 64, 2);   // J=256, M=4096, B=2
    k_sgemm<<<gkv, 256>>>(x_kv, 1L, (long)NN, (long)CN,
                          w_kv,      512, 0L, b_kv,      nullptr,
                          kfull, (long)CC, 1L, (long)CN, CC);
    k_sgemm<<<gkv, 256>>>(x_kv, 1L, (long)NN, (long)CN,
                          w_kv+CC,   512, 0L, b_kv+CC,   nullptr,
                          vfull, (long)CC, 1L, (long)CN, CC);
    k_sgemm<<<gkv, 256>>>(x_q,  1L, (long)NN, (long)CN,
                          w_q,       256, 0L, b_q,       nullptr,
                          q,     (long)CC, 1L, (long)CN, CC);

    k_gather<<<BATCH*KTOP*64/256, 256>>>();

    // residual conv branch
    k_transpose<<<dim3(128, 8, 2), dim3(32, 8)>>>();
    k_dwconv<<<BATCH*CN/256, 256>>>(w_dw, b_dw);
    // pw: M=o(256), J=n(4096), K=c(256); A=w_pw row-major, B=dw[b] (c x n)
    k_sgemm<<<dim3(64, 4, 2), 256>>>(w_pw, 256L, 1L, 0L,
                                     dw,   4096, (long)CN, nullptr, b_pw,
                                     res,  4096L, 1L, (long)CN, CC);

    // attention
    k_attn<<<dim3(8, 32, 2), 128>>>();

    // proj: writes directly into d_out in (B,C,D,H,W) = [b][j][n] layout
    k_sgemm<<<dim3(4, 64, 2), 256>>>(attn, 256L, 1L, (long)CN,
                                     w_proj, 256, 0L, b_proj, nullptr,
                                     out, 1L, 4096L, (long)CN, CC);

    k_add<<<BATCH*CN/256, 256>>>(out);
}

// round 3
// speedup vs baseline: 1.5878x; 1.5878x over previous
#include <cuda_runtime.h>
#include <math.h>

#define BATCH 2
#define CC 256
#define NN 4096
#define HEADS 32
#define HD 8
#define KTOP 512
#define CN (CC*NN)

// ---------------- scratch (device globals; no allocation) ----------------
__device__ float g_avgmax[BATCH*2*NN];
__device__ float g_scores[BATCH*NN];
__device__ int   g_idx[BATCH*KTOP];
__device__ float g_q[BATCH*NN*CC];
__device__ float g_kg[BATCH*KTOP*CC];
__device__ float g_vg[BATCH*KTOP*CC];
__device__ float g_attn[BATCH*NN*CC];
__device__ float g_vvol[BATCH*CN];
__device__ float g_dw[BATCH*CN];
__device__ float g_res[BATCH*CN];

// ---------------- 1. channel avg/max reduce (4-way c-split) ----------------
__global__ void k_reduce(const float* __restrict__ x) {
    __shared__ float ssum[4][64], smax[4][64];
    int b = blockIdx.y;
    int n0 = blockIdx.x * 64;
    int cq = threadIdx.x >> 6;     // 0..3
    int nn = threadIdx.x & 63;
    const float* p = x + (long)b*CN + n0 + nn;
    float s = 0.f, mx = -INFINITY;
#pragma unroll 8
    for (int c = cq*64; c < cq*64 + 64; c++) {
        float v = p[(long)c*NN]; s += v; mx = fmaxf(mx, v);
    }
    ssum[cq][nn] = s; smax[cq][nn] = mx;
    __syncthreads();
    if (cq == 0) {
        s = ssum[0][nn] + ssum[1][nn] + ssum[2][nn] + ssum[3][nn];
        mx = fmaxf(fmaxf(smax[0][nn], smax[1][nn]), fmaxf(smax[2][nn], smax[3][nn]));
        g_avgmax[(b*2+0)*NN + n0 + nn] = s * (1.0f/CC);
        g_avgmax[(b*2+1)*NN + n0 + nn] = mx;
    }
}

// ---------------- 2. 7x7x7 spatial conv (2ch -> 1ch) + sigmoid ----------------
__global__ void k_spa(const float* __restrict__ w_spa) {
    __shared__ float w[686];
    int tid = threadIdx.x;
    for (int l = tid; l < 686; l += blockDim.x) w[l] = w_spa[l];
    __syncthreads();
    int i = blockIdx.x * blockDim.x + tid;
    if (i >= BATCH*NN) return;
    int b = i >> 12, n = i & (NN-1);
    int z = n >> 8, y = (n >> 4) & 15, x0 = n & 15;
    float s = 0.f;
    for (int ci = 0; ci < 2; ci++) {
        const float* in = g_avgmax + (b*2+ci)*NN;
        const float* wc = w + ci*343;
        for (int dz = 0; dz < 7; dz++) {
            int zz = z + dz - 3; if (zz < 0 || zz > 15) continue;
            for (int dy = 0; dy < 7; dy++) {
                int yy = y + dy - 3; if (yy < 0 || yy > 15) continue;
                const float* row = in + zz*256 + yy*16;
                const float* wr = wc + dz*49 + dy*7;
                for (int dx = 0; dx < 7; dx++) {
                    int xx = x0 + dx - 3; if (xx < 0 || xx > 15) continue;
                    s += wr[dx] * row[xx];
                }
            }
        }
    }
    g_scores[i] = 1.0f / (1.0f + __expf(-s));
}

// ---------------- 3. per-batch top-512 via bitonic sort ----------------
__global__ void k_topk() {
    __shared__ float key[NN];
    __shared__ int   val[NN];
    int b = blockIdx.x, tid = threadIdx.x;
    for (int i = tid; i < NN; i += blockDim.x) { key[i] = g_scores[b*NN + i]; val[i] = i; }
    __syncthreads();
    for (int k = 2; k <= NN; k <<= 1) {
        for (int j = k >> 1; j > 0; j >>= 1) {
            for (int i = tid; i < NN; i += blockDim.x) {
                int ixj = i ^ j;
                if (ixj > i) {
                    bool desc = ((i & k) == 0);
                    float a = key[i], c2 = key[ixj];
                    bool sw = desc ? (a < c2) : (a > c2);
                    if (sw) {
                        key[i] = c2; key[ixj] = a;
                        int t = val[i]; val[i] = val[ixj]; val[ixj] = t;
                    }
                }
            }
            __syncthreads();
        }
    }
    for (int i = tid; i < KTOP; i += blockDim.x) g_idx[b*KTOP + i] = val[i];
}

// ---------------- tiled SGEMM: 128x128 tile, 8x8 microtile, double-buffered ----
// C[b][m][j] = sum_k A[b][m][k] * Bw[b][k][j] (+bias_j[j] +bias_m[m] +addend[off])
// A element  : A[b*a_bs + m*a_ms + k*a_ks]   (a_ks==1 row-major OR a_ms==1 m-contig)
// rowidx     : optional gather: A row m -> rowidx[b*ridx_bs + m] (m-contig layout)
// Bw element : Bw[b*w_bs + k*ldb + j]
// C element  : C[b*c_bs + m*c_ms + j*c_js]
__global__ void __launch_bounds__(256) k_sgemm(
    const float* __restrict__ A, long a_ms, long a_ks, long a_bs,
    const int* __restrict__ rowidx, long ridx_bs,
    const float* __restrict__ Bw, int ldb, long w_bs,
    const float* __restrict__ bias_j, const float* __restrict__ bias_m,
    const float* __restrict__ addend,
    float* __restrict__ Cc, long c_ms, long c_js, long c_bs,
    int K)
{
    __shared__ float As[2][8][132];
    __shared__ float Bs[2][8][132];
    __shared__ int   sidx[128];

    int tid = threadIdx.x;
    int m0 = blockIdx.y * 128, j0 = blockIdx.x * 128;
    const float* Ab = A  + (long)blockIdx.z * a_bs;
    const float* Bb = Bw + (long)blockIdx.z * w_bs;

    int mode = rowidx ? 2 : ((a_ks == 1) ? 0 : 1);

    // compute-thread mapping: 8 warps as 4x2 grid of 32x64; lane as 4x8 of 8x8 tiles
    int warp = tid >> 5, lane = tid & 31;
    int tm = (warp & 3) * 32 + (lane & 3) * 8;
    int tn = (warp >> 2) * 64 + (lane >> 2) * 8;

    // loader mapping
    int am  = tid >> 1, ak = (tid & 1) * 4;     // mode 0 (row-major)
    int am4 = (tid & 31) * 4, ak2 = tid >> 5;   // mode 1 (m-contig)
    int bj4 = (tid & 31) * 4, bk  = tid >> 5;   // B

    long goff[4]; int gmm[4], gkk[4];
    if (mode == 2) {
        if (tid < 128) sidx[tid] = rowidx[(long)blockIdx.z * ridx_bs + m0 + tid];
        __syncthreads();
#pragma unroll
        for (int r = 0; r < 4; r++) {
            int l = tid + r * 256;
            gmm[r] = l & 127; gkk[r] = l >> 7;
            goff[r] = (long)gkk[r] * a_ks + sidx[gmm[r]];
        }
    }

    const float* pA = Ab;
    if (mode == 0)      pA = Ab + (long)(m0 + am) * a_ms + ak;
    else if (mode == 1) pA = Ab + (long)ak2 * a_ks + m0 + am4;
    const float* pB = Bb + (long)bk * ldb + j0 + bj4;

    float fa[4]; float4 fb;
    auto fetch = [&](int t) {
        long k0 = (long)t * 8;
        if (mode == 0) {
            float4 v = *(const float4*)(pA + k0);
            fa[0]=v.x; fa[1]=v.y; fa[2]=v.z; fa[3]=v.w;
        } else if (mode == 1) {
            float4 v = *(const float4*)(pA + k0 * a_ks);
            fa[0]=v.x; fa[1]=v.y; fa[2]=v.z; fa[3]=v.w;
        } else {
#pragma unroll
            for (int r = 0; r < 4; r++) fa[r] = Ab[k0 * a_ks + goff[r]];
        }
        fb = *(const float4*)(pB + (long)t * 8 * ldb);
    };
    auto stos = [&](int bs) {
        if (mode == 0) {
            As[bs][ak+0][am]=fa[0]; As[bs][ak+1][am]=fa[1];
            As[bs][ak+2][am]=fa[2]; As[bs][ak+3][am]=fa[3];
        } else if (mode == 1) {
            *(float4*)&As[bs][ak2][am4] = make_float4(fa[0],fa[1],fa[2],fa[3]);
        } else {
#pragma unroll
            for (int r = 0; r < 4; r++) As[bs][gkk[r]][gmm[r]] = fa[r];
        }
        *(float4*)&Bs[bs][bk][bj4] = fb;
    };

    float acc[8][8] = {};
    fetch(0); stos(0);
    __syncthreads();

    int nk = K >> 3, buf = 0;
    for (int t = 0; t < nk; t++) {
        bool more = (t + 1 < nk);
        if (more) fetch(t + 1);
#pragma unroll
        for (int kk = 0; kk < 8; kk++) {
            float av[8], bv[8];
            *(float4*)(av)   = *(const float4*)&As[buf][kk][tm];
            *(float4*)(av+4) = *(const float4*)&As[buf][kk][tm+4];
            *(float4*)(bv)   = *(const float4*)&Bs[buf][kk][tn];
            *(float4*)(bv+4) = *(const float4*)&Bs[buf][kk][tn+4];
#pragma unroll
            for (int i = 0; i < 8; i++)
#pragma unroll
                for (int j = 0; j < 8; j++)
                    acc[i][j] += av[i] * bv[j];
        }
        if (more) { stos(buf ^ 1); __syncthreads(); buf ^= 1; }
    }

    float bj[8], bm[8];
#pragma unroll
    for (int j = 0; j < 8; j++) bj[j] = bias_j ? bias_j[j0+tn+j] : 0.f;
#pragma unroll
    for (int i = 0; i < 8; i++) bm[i] = bias_m ? bias_m[m0+tm+i] : 0.f;
    long cb = (long)blockIdx.z * c_bs;
    if (c_js == 1) {
#pragma unroll
        for (int i = 0; i < 8; i++) {
            long off = cb + (long)(m0+tm+i)*c_ms + (j0+tn);
            float4 v0 = make_float4(acc[i][0]+bj[0]+bm[i], acc[i][1]+bj[1]+bm[i],
                                    acc[i][2]+bj[2]+bm[i], acc[i][3]+bj[3]+bm[i]);
            float4 v1 = make_float4(acc[i][4]+bj[4]+bm[i], acc[i][5]+bj[5]+bm[i],
                                    acc[i][6]+bj[6]+bm[i], acc[i][7]+bj[7]+bm[i]);
            if (addend) {
                float4 a0 = *(const float4*)&addend[off];
                float4 a1 = *(const float4*)&addend[off+4];
                v0.x+=a0.x; v0.y+=a0.y; v0.z+=a0.z; v0.w+=a0.w;
                v1.x+=a1.x; v1.y+=a1.y; v1.z+=a1.z; v1.w+=a1.w;
            }
            *(float4*)&Cc[off]   = v0;
            *(float4*)&Cc[off+4] = v1;
        }
    } else {
#pragma unroll
        for (int i = 0; i < 8; i++)
#pragma unroll
            for (int j = 0; j < 8; j++) {
                long off = cb + (long)(m0+tm+i)*c_ms + (long)(j0+tn+j)*c_js;
                float v = acc[i][j] + bj[j] + bm[i];
                if (addend) v += addend[off];
                Cc[off] = v;
            }
    }
}

// ---------------- gather V rows (from vvol, transposed read) ----------------
__global__ void k_gatherv() {
    int t = blockIdx.x * blockDim.x + threadIdx.x;   // BATCH*KTOP*CC
    if (t >= BATCH*KTOP*CC) return;
    int c = t & 255, k = (t >> 8) & 511, b = t >> 17;
    g_vg[t] = g_vvol[(long)b*CN + (long)c*NN + g_idx[b*KTOP + k]];
}

// ---------------- depthwise 3x3x3 conv (4 outputs/thread, float4 rows) -------
__global__ void k_dwconv(const float* __restrict__ w_dw, const float* __restrict__ b_dw) {
    int i = blockIdx.x * blockDim.x + threadIdx.x;   // BATCH*CC*16*16*4
    int xq = i & 3, y = (i >> 2) & 15, z = (i >> 6) & 15, c = (i >> 10) & 255, b = i >> 18;
    const float* base = g_vvol + ((long)b*CC + c)*NN;
    float w27[27];
#pragma unroll
    for (int t = 0; t < 27; t++) w27[t] = w_dw[c*27 + t];
    float bias = b_dw[c];
    float o0 = bias, o1 = bias, o2 = bias, o3 = bias;
    int x0 = xq * 4;
#pragma unroll
    for (int dz = 0; dz < 3; dz++) {
        int zz = z + dz - 1; if (zz < 0 || zz > 15) continue;
#pragma unroll
        for (int dy = 0; dy < 3; dy++) {
            int yy = y + dy - 1; if (yy < 0 || yy > 15) continue;
            const float* r = base + zz*256 + yy*16 + x0;
            float4 m4 = *(const float4*)r;
            float xl = (xq > 0) ? r[-1] : 0.f;
            float xr = (xq < 3) ? r[4]  : 0.f;
            float wl = w27[dz*9+dy*3], wm = w27[dz*9+dy*3+1], wr = w27[dz*9+dy*3+2];
            o0 += wl*xl   + wm*m4.x + wr*m4.y;
            o1 += wl*m4.x + wm*m4.y + wr*m4.z;
            o2 += wl*m4.y + wm*m4.z + wr*m4.w;
            o3 += wl*m4.z + wm*m4.w + wr*xr;
        }
    }
    *(float4*)&g_dw[((long)b*CC + c)*NN + z*256 + y*16 + x0] = make_float4(o0,o1,o2,o3);
}

// ---------------- attention: plain softmax (no max), 4 queries/thread --------
__global__ void __launch_bounds__(256) k_attn() {
    __shared__ float Ks[KTOP*HD];   // 16 KB
    __shared__ float Vs[KTOP*HD];   // 16 KB
    int b = blockIdx.z, h = blockIdx.y, nt = blockIdx.x;
    int tid = threadIdx.x;
    const float* kgb = g_kg + (long)b*KTOP*CC + h*HD;
    const float* vgb = g_vg + (long)b*KTOP*CC + h*HD;
    for (int k = tid; k < KTOP; k += 256) {
        *(float4*)(Ks + k*8)     = *(const float4*)(kgb + (long)k*CC);
        *(float4*)(Ks + k*8 + 4) = *(const float4*)(kgb + (long)k*CC + 4);
        *(float4*)(Vs + k*8)     = *(const float4*)(vgb + (long)k*CC);
        *(float4*)(Vs + k*8 + 4) = *(const float4*)(vgb + (long)k*CC + 4);
    }
    __syncthreads();
    const float scale = 0.35355339059327373f;  // 8^-0.5
    float qr[4][8], l[4] = {0,0,0,0}, acc[4][8] = {};
    int n0 = nt * 1024;
#pragma unroll
    for (int i = 0; i < 4; i++) {
        int n = n0 + tid + 256*i;
        const float* qp = g_q + ((long)b*NN + n)*CC + h*HD;
        float4 qa = *(const float4*)qp;
        float4 qb = *(const float4*)(qp + 4);
        qr[i][0]=qa.x*scale; qr[i][1]=qa.y*scale; qr[i][2]=qa.z*scale; qr[i][3]=qa.w*scale;
        qr[i][4]=qb.x*scale; qr[i][5]=qb.y*scale; qr[i][6]=qb.z*scale; qr[i][7]=qb.w*scale;
    }
#pragma unroll 2
    for (int k = 0; k < KTOP; k++) {
        float4 ka = *(const float4*)(Ks + k*8);
        float4 kb = *(const float4*)(Ks + k*8 + 4);
        float4 va = *(const float4*)(Vs + k*8);
        float4 vb = *(const float4*)(Vs + k*8 + 4);
#pragma unroll
        for (int i = 0; i < 4; i++) {
            float s = qr[i][0]*ka.x + qr[i][1]*ka.y + qr[i][2]*ka.z + qr[i][3]*ka.w
                    + qr[i][4]*kb.x + qr[i][5]*kb.y + qr[i][6]*kb.z + qr[i][7]*kb.w;
            float p = __expf(s);
            l[i] += p;
            acc[i][0] += p*va.x; acc[i][1] += p*va.y;
            acc[i][2] += p*va.z; acc[i][3] += p*va.w;
            acc[i][4] += p*vb.x; acc[i][5] += p*vb.y;
            acc[i][6] += p*vb.z; acc[i][7] += p*vb.w;
        }
    }
#pragma unroll
    for (int i = 0; i < 4; i++) {
        int n = n0 + tid + 256*i;
        float inv = 1.0f / l[i];
        float* op = g_attn + ((long)b*NN + n)*CC + h*HD;
        *(float4*)op       = make_float4(acc[i][0]*inv, acc[i][1]*inv, acc[i][2]*inv, acc[i][3]*inv);
        *(float4*)(op + 4) = make_float4(acc[i][4]*inv, acc[i][5]*inv, acc[i][6]*inv, acc[i][7]*inv);
    }
}

// ---------------- launcher ----------------
extern "C" void kernel_launch(void* const* d_in, const int* in_sizes, int n_in,
                              void* d_out, int out_size) {
    const float* x_kv  = (const float*)d_in[0];
    const float* x_q   = (const float*)d_in[1];
    const float* w_spa = (const float*)d_in[2];
    const float* w_kv  = (const float*)d_in[3];
    const float* b_kv  = (const float*)d_in[4];
    const float* w_q   = (const float*)d_in[5];
    const float* b_q   = (const float*)d_in[6];
    const float* w_proj= (const float*)d_in[7];
    const float* b_proj= (const float*)d_in[8];
    const float* w_dw  = (const float*)d_in[9];
    const float* b_dw  = (const float*)d_in[10];
    const float* w_pw  = (const float*)d_in[11];
    const float* b_pw  = (const float*)d_in[12];
    float* out = (float*)d_out;

    float *q, *kg, *attn, *vvol, *dw, *res;
    int *idx;
    cudaGetSymbolAddress((void**)&q,    g_q);
    cudaGetSymbolAddress((void**)&kg,   g_kg);
    cudaGetSymbolAddress((void**)&attn, g_attn);
    cudaGetSymbolAddress((void**)&vvol, g_vvol);
    cudaGetSymbolAddress((void**)&dw,   g_dw);
    cudaGetSymbolAddress((void**)&res,  g_res);
    cudaGetSymbolAddress((void**)&idx,  g_idx);

    // scoring path
    k_reduce<<<dim3(64, 2), 256>>>(x_kv);
    k_spa<<<32, 256>>>(w_spa);
    k_topk<<<2, 1024>>>();

    // Q projection: A = x_q (m contiguous), C = q row-major (B,N,C)
    k_sgemm<<<dim3(2, 32, 2), 256>>>(x_q, 1L, (long)NN, (long)CN, nullptr, 0L,
                                     w_q, 256, 0L, b_q, nullptr, nullptr,
                                     q, (long)CC, 1L, (long)CN, CC);

    // V projection: writes DIRECTLY in (B,C,N) layout -> g_vvol (no transpose)
    k_sgemm<<<dim3(2, 32, 2), 256>>>(x_kv, 1L, (long)NN, (long)CN, nullptr, 0L,
                                     w_kv + CC, 512, 0L, b_kv + CC, nullptr, nullptr,
                                     vvol, 1L, (long)NN, (long)CN, CC);

    // K projection: ONLY on gathered top-512 rows -> g_kg (B,KTOP,C)
    k_sgemm<<<dim3(2, 4, 2), 256>>>(x_kv, 1L, (long)NN, (long)CN, idx, (long)KTOP,
                                    w_kv, 512, 0L, b_kv, nullptr, nullptr,
                                    kg, (long)CC, 1L, (long)(KTOP*CC), CC);

    // gather V from vvol (transposed read)
    k_gatherv<<<BATCH*KTOP*CC/256, 256>>>();

    // residual conv branch
    k_dwconv<<<BATCH*CC*NN/4/256, 256>>>(w_dw, b_dw);
    k_sgemm<<<dim3(32, 2, 2), 256>>>(w_pw, 256L, 1L, 0L, nullptr, 0L,
                                     dw, 4096, (long)CN, nullptr, b_pw, nullptr,
                                     res, 4096L, 1L, (long)CN, CC);

    // attention
    k_attn<<<dim3(4, 32, 2), 256>>>();

    // proj GEMM: out[b][j][n] = attn@w_proj + b_proj + res  (residual fused)
    k_sgemm<<<dim3(2, 32, 2), 256>>>(attn, 256L, 1L, (long)CN, nullptr, 0L,
                                     w_proj, 256, 0L, b_proj, nullptr, res,
                                     out, 1L, 4096L, (long)CN, CC);
}